// round 8
// baseline (speedup 1.0000x reference)
#include <cuda_runtime.h>

#define NPW      2048      // 65536 points / 32 bits (words per proposal row)
#define PTOT_MAX 512
#define BMAX     8
#define MAXP     128

__device__ unsigned g_pc_bits[PTOT_MAX * NPW];   // 4 MB bitmask; zeroed-on-read by k_reduce
__device__ unsigned g_ref_bits[BMAX * NPW];      // per-scene reference bitmask (fully rewritten)
__device__ int      g_offs[BMAX + 1];
__device__ unsigned g_pcnt[PTOT_MAX];            // per-proposal |pc| accumulator
__device__ unsigned g_pits[PTOT_MAX];            // per-proposal |pc & ref|
__device__ unsigned g_prs[PTOT_MAX];             // per-proposal |ref| (of its scene)
__device__ int      g_ctr;

// ---- Kernel A: scatter (2 pairs/thread, RED.OR) + ref ballot init + zero accumulators ----
__global__ void __launch_bounds__(256, 8)
k_main(const int4* __restrict__ pidx2, const int2* __restrict__ pidx,
       const int* __restrict__ labels, const int* __restrict__ object_id,
       const int* __restrict__ pes,
       int M, int M2, int B, int npoint, int n_total, unsigned npu) {
    int t = blockIdx.x * blockDim.x + threadIdx.x;

    if (t == 0) {
        g_offs[0] = 0;
        for (int b = 0; b < B; b++) g_offs[b + 1] = g_offs[b] + __ldg(&pes[b]);
        g_ctr = 0;
    }
    if (t < PTOT_MAX) { g_pcnt[t] = 0u; g_pits[t] = 0u; g_prs[t] = 0u; }

    // --- reference bitmask via warp ballot (one label per thread) ---
    if (t < n_total) {
        int b = t / npoint;
        int oid = __ldg(&object_id[b]);
        int jl = t - b * npoint;
        unsigned wbase = (unsigned)(t & ~31);
        if (wbase + 32 <= (unsigned)n_total) {        // full warp, same scene (npoint%32==0)
            unsigned bits = __ballot_sync(0xffffffffu, __ldg(&labels[t]) == oid);
            if ((t & 31) == 0) g_ref_bits[b * NPW + (jl >> 5)] = bits;
        } else {                                      // ragged tail fallback
            if (__ldg(&labels[t]) == oid)
                atomicOr(&g_ref_bits[b * NPW + (jl >> 5)], 1u << (jl & 31u));
        }
    }

    // --- scatter: set bit (pid, j % npoint) ---
    if (t < M2) {
        int4 a = __ldg(&pidx2[t]);                    // two (pid, j) pairs
        unsigned j0 = (unsigned)a.y % npu;
        unsigned j1 = (unsigned)a.w % npu;
        atomicOr(&g_pc_bits[(size_t)a.x * NPW + (j0 >> 5)], 1u << (j0 & 31u));
        atomicOr(&g_pc_bits[(size_t)a.z * NPW + (j1 >> 5)], 1u << (j1 & 31u));
    }
    if ((M & 1) && t == M2) {                         // odd tail pair
        int2 v = __ldg(&pidx[M - 1]);
        unsigned j = (unsigned)v.y % npu;
        atomicOr(&g_pc_bits[(size_t)v.x * NPW + (j >> 5)], 1u << (j & 31u));
    }
}

// ---- Kernel B: CPB CTAs per proposal, one uint4 per thread (max chip MLP),
//      partial popcounts RED.ADD'd per proposal; last block computes IoU + outputs.
// Output layout (f32): [B*MAXP*C clus_feats | B*C select_feats | B sel_idx | B+1 offsets | B good]
__global__ void __launch_bounds__(128, 8)
k_reduce_final(int B, int npw, int PTOT, int C, int cpb,
               const float* __restrict__ feats,
               const int* __restrict__ pes,
               float* __restrict__ out) {
    int tid = threadIdx.x;
    int p = blockIdx.x / cpb;
    int chunk = blockIdx.x - p * cpb;

    // scene id of this proposal
    int b = 0;
    #pragma unroll
    for (int k = 1; k <= BMAX; k++) b += (k <= B && g_offs[k] <= p) ? 1 : 0;
    if (b >= B) b = B - 1;

    int nq = npw >> 2;                               // uint4 chunks per row
    int w = chunk * 128 + tid;
    unsigned cnt = 0, its = 0, rs = 0;
    if (w < nq) {
        uint4* pcq = (uint4*)(g_pc_bits + (size_t)p * NPW) + w;
        const uint4* __restrict__ refq = (const uint4*)(g_ref_bits + (size_t)b * NPW) + w;
        uint4 v = *pcq;
        uint4 r = __ldg(refq);
        *pcq = make_uint4(0u, 0u, 0u, 0u);           // self-clean for next replay
        cnt = __popc(v.x) + __popc(v.y) + __popc(v.z) + __popc(v.w);
        its = __popc(v.x & r.x) + __popc(v.y & r.y)
            + __popc(v.z & r.z) + __popc(v.w & r.w);
        rs  = __popc(r.x) + __popc(r.y) + __popc(r.z) + __popc(r.w);
    }
    if (chunk == 0 && tid < (npw & 3)) {             // word tail (npw % 4)
        int w0 = (nq << 2) + tid;
        unsigned v = g_pc_bits[(size_t)p * NPW + w0];
        unsigned r = g_ref_bits[(size_t)b * NPW + w0];
        g_pc_bits[(size_t)p * NPW + w0] = 0u;
        cnt += __popc(v); its += __popc(v & r); rs += __popc(r);
    }
    cnt = __reduce_add_sync(0xffffffffu, cnt);
    its = __reduce_add_sync(0xffffffffu, its);
    rs  = __reduce_add_sync(0xffffffffu, rs);
    __shared__ unsigned sc[4], si[4], sr[4];
    int warp = tid >> 5;
    if ((tid & 31) == 0) { sc[warp] = cnt; si[warp] = its; sr[warp] = rs; }
    __syncthreads();
    if (tid == 0) {
        unsigned Ct = sc[0] + sc[1] + sc[2] + sc[3];
        unsigned It = si[0] + si[1] + si[2] + si[3];
        unsigned Rt = sr[0] + sr[1] + sr[2] + sr[3];
        atomicAdd(&g_pcnt[p], Ct);                   // RED.ADD: 4 contributors/address
        atomicAdd(&g_pits[p], It);
        atomicAdd(&g_prs[p],  Rt);
    }

    // ---- last-block-done epilogue ----
    __syncthreads();
    __shared__ int s_last;
    if (tid == 0) {
        __threadfence();
        s_last = (atomicAdd(&g_ctr, 1) == (int)gridDim.x - 1) ? 1 : 0;
    }
    __syncthreads();
    if (!s_last) return;

    __shared__ float s_iou[PTOT_MAX];
    for (int p2 = tid; p2 < PTOT; p2 += 128) {
        float inter = (float)g_pits[p2];
        float uni = (float)g_pcnt[p2] + (float)g_prs[p2] - inter;
        s_iou[p2] = (uni > 0.0f) ? inter / fmaxf(uni, 1.0f) : 0.0f;
    }
    __syncthreads();

    __shared__ int   s_best[BMAX];
    __shared__ float s_max[BMAX];
    if (tid < B) {
        int lo = g_offs[tid], hi = g_offs[tid + 1];
        int best = -1; float mx = -1.0f;
        for (int p2 = lo; p2 < hi; p2++) {
            float v = s_iou[p2];
            if (v > mx) { mx = v; best = p2; }       // strict >: first max wins
        }
        s_best[tid] = (__ldg(&pes[tid]) > 0) ? best : -1;
        s_max[tid] = mx;
    }
    __syncthreads();
    int clus_n   = B * MAXP * C;
    int sf_off   = clus_n;
    int spi_off  = sf_off + B * C;
    int offs_off = spi_off + B;
    int good_off = offs_off + B + 1;
    int mc = MAXP * C;
    for (int idx = tid; idx < clus_n; idx += 128) {
        int b2 = idx / mc, rem = idx - b2 * mc;
        int slot = rem / C, c = rem - slot * C;
        int pp = g_offs[b2] + slot;
        out[idx] = (pp < g_offs[b2 + 1]) ? __ldg(&feats[(size_t)pp * C + c]) : 0.0f;
    }
    for (int idx = tid; idx < B * C; idx += 128) {
        int b2 = idx / C, c = idx - b2 * C;
        int sel = s_best[b2];
        out[sf_off + idx] = (sel >= 0) ? __ldg(&feats[(size_t)sel * C + c]) : 0.0f;
    }
    if (tid < B)  out[spi_off + tid]  = (float)s_best[tid];
    if (tid <= B) out[offs_off + tid] = (float)g_offs[tid];
    if (tid < B)  out[good_off + tid] = ((s_max[tid] > 0.2f) && (__ldg(&pes[tid]) > 0)) ? 1.0f : 0.0f;
}

extern "C" void kernel_launch(void* const* d_in, const int* in_sizes, int n_in,
                              void* d_out, int out_size) {
    const int*   pidx   = (const int*)d_in[0];   // [M,2] int32
    const int*   pes    = (const int*)d_in[1];   // [B] int32
    const int*   labels = (const int*)d_in[2];   // [B*npoint] int32
    const int*   oid    = (const int*)d_in[3];   // [B] int32
    const float* feats  = (const float*)d_in[4]; // [PTOT, C] f32
    float* out = (float*)d_out;

    int M       = in_sizes[0] / 2;
    int B       = in_sizes[1];
    int n_total = in_sizes[2];
    int npoint  = n_total / B;
    int C       = 32;
    int PTOT    = in_sizes[4] / C;
    int npw     = (npoint + 31) / 32;

    int M2 = M / 2;
    int workA = M2 + 1;                       // +1 covers the odd-tail thread
    if (workA < n_total) workA = n_total;
    int gridA = (workA + 255) / 256;
    k_main<<<gridA, 256>>>((const int4*)pidx, (const int2*)pidx, labels, oid, pes,
                           M, M2, B, npoint, n_total, (unsigned)npoint);

    int nq = npw >> 2;
    int cpb = (nq + 127) / 128;               // CTAs per proposal (4 for npoint=65536)
    if (cpb < 1) cpb = 1;
    k_reduce_final<<<PTOT * cpb, 128>>>(B, npw, PTOT, C, cpb, feats, pes, out);
}

// round 9
// speedup vs baseline: 1.3161x; 1.3161x over previous
#include <cuda_runtime.h>

#define NPW      2048      // 65536 points / 32 bits (words per proposal row)
#define PTOT_MAX 512
#define BMAX     8
#define MAXP     128

__device__ unsigned g_pc_bits[PTOT_MAX * NPW];   // 4 MB bitmask; zeroed-on-read by k_reduce
__device__ unsigned g_ref_bits[BMAX * NPW];      // per-scene reference bitmask (fully rewritten)
__device__ int      g_offs[BMAX + 1];
__device__ float    g_iou[PTOT_MAX];

// ---- Kernel A: scatter (2 pairs/thread, RED.OR) + ref ballot init + offsets ----
__global__ void __launch_bounds__(256, 8)
k_main(const int4* __restrict__ pidx2, const int2* __restrict__ pidx,
       const int* __restrict__ labels, const int* __restrict__ object_id,
       const int* __restrict__ pes,
       int M, int M2, int B, int npoint, int n_total, unsigned npu) {
    int t = blockIdx.x * blockDim.x + threadIdx.x;

    if (t == 0) {
        g_offs[0] = 0;
        for (int b = 0; b < B; b++) g_offs[b + 1] = g_offs[b] + __ldg(&pes[b]);
    }

    // --- reference bitmask via warp ballot (one label per thread) ---
    if (t < n_total) {
        int b = t / npoint;
        int oid = __ldg(&object_id[b]);
        int jl = t - b * npoint;
        unsigned wbase = (unsigned)(t & ~31);
        if (wbase + 32 <= (unsigned)n_total) {        // full warp, same scene (npoint%32==0)
            unsigned bits = __ballot_sync(0xffffffffu, __ldg(&labels[t]) == oid);
            if ((t & 31) == 0) g_ref_bits[b * NPW + (jl >> 5)] = bits;
        } else {                                      // ragged tail fallback
            if (__ldg(&labels[t]) == oid)
                atomicOr(&g_ref_bits[b * NPW + (jl >> 5)], 1u << (jl & 31u));
        }
    }

    // --- scatter: set bit (pid, j % npoint) ---
    if (t < M2) {
        int4 a = __ldg(&pidx2[t]);                    // two (pid, j) pairs
        unsigned j0 = (unsigned)a.y % npu;
        unsigned j1 = (unsigned)a.w % npu;
        atomicOr(&g_pc_bits[(size_t)a.x * NPW + (j0 >> 5)], 1u << (j0 & 31u));
        atomicOr(&g_pc_bits[(size_t)a.z * NPW + (j1 >> 5)], 1u << (j1 & 31u));
    }
    if ((M & 1) && t == M2) {                         // odd tail pair
        int2 v = __ldg(&pidx[M - 1]);
        unsigned j = (unsigned)v.y % npu;
        atomicOr(&g_pc_bits[(size_t)v.x * NPW + (j >> 5)], 1u << (j & 31u));
    }
}

// ---- Kernel B: block-per-proposal AND-popcount (uint4, 2/thread) + zero-on-read.
//      Clean kernel: no fence, no cross-block sync (R2 shape: 9.2us flushed).
__global__ void __launch_bounds__(256, 8)
k_reduce(int B, int npw) {
    int p = blockIdx.x;                              // proposal id (grid == PTOT)
    int tid = threadIdx.x;

    int b = 0;
    #pragma unroll
    for (int k = 1; k <= BMAX; k++) b += (k <= B && g_offs[k] <= p) ? 1 : 0;
    if (b >= B) b = B - 1;

    uint4* pcrow = (uint4*)(g_pc_bits + (size_t)p * NPW);
    const uint4* __restrict__ refrow = (const uint4*)(g_ref_bits + (size_t)b * NPW);
    int nq = npw >> 2;                               // uint4 chunks per row (512)
    unsigned cnt = 0, its = 0, rs = 0;
    const uint4 z = make_uint4(0u, 0u, 0u, 0u);
    #pragma unroll 2
    for (int w = tid; w < nq; w += 256) {
        uint4 v = pcrow[w];
        uint4 r = __ldg(&refrow[w]);
        pcrow[w] = z;                                // self-clean for next replay
        cnt += __popc(v.x) + __popc(v.y) + __popc(v.z) + __popc(v.w);
        its += __popc(v.x & r.x) + __popc(v.y & r.y)
             + __popc(v.z & r.z) + __popc(v.w & r.w);
        rs  += __popc(r.x) + __popc(r.y) + __popc(r.z) + __popc(r.w);
    }
    // word tail if npw % 4 != 0
    for (int w0 = (nq << 2) + tid; w0 < npw; w0 += 256) {
        unsigned v = g_pc_bits[(size_t)p * NPW + w0];
        unsigned r = g_ref_bits[(size_t)b * NPW + w0];
        g_pc_bits[(size_t)p * NPW + w0] = 0u;
        cnt += __popc(v); its += __popc(v & r); rs += __popc(r);
    }
    cnt = __reduce_add_sync(0xffffffffu, cnt);
    its = __reduce_add_sync(0xffffffffu, its);
    rs  = __reduce_add_sync(0xffffffffu, rs);
    __shared__ unsigned sc[8], si[8], sr[8];
    int warp = tid >> 5;
    if ((tid & 31) == 0) { sc[warp] = cnt; si[warp] = its; sr[warp] = rs; }
    __syncthreads();
    if (tid == 0) {
        unsigned Ct = 0, It = 0, Rt = 0;
        #pragma unroll
        for (int w = 0; w < 8; w++) { Ct += sc[w]; It += si[w]; Rt += sr[w]; }
        float inter = (float)It;
        float uni = (float)Ct + (float)Rt - inter;
        g_iou[p] = (uni > 0.0f) ? inter / fmaxf(uni, 1.0f) : 0.0f;
    }
}

// ---- Kernel C: single-block epilogue — argmax + all output writes.
// Output layout (f32): [B*MAXP*C clus_feats | B*C select_feats | B sel_idx | B+1 offsets | B good]
__global__ void k_final(const float* __restrict__ feats, const int* __restrict__ pes,
                        int B, int C, float* __restrict__ out) {
    __shared__ int   s_best[BMAX];
    __shared__ float s_max[BMAX];
    int tid = threadIdx.x;
    if (tid < B) {
        int lo = g_offs[tid], hi = g_offs[tid + 1];
        int best = -1; float mx = -1.0f;
        for (int p = lo; p < hi; p++) {
            float v = g_iou[p];
            if (v > mx) { mx = v; best = p; }        // strict >: first max wins
        }
        s_best[tid] = (__ldg(&pes[tid]) > 0) ? best : -1;
        s_max[tid] = mx;
    }
    __syncthreads();
    int clus_n   = B * MAXP * C;
    int sf_off   = clus_n;
    int spi_off  = sf_off + B * C;
    int offs_off = spi_off + B;
    int good_off = offs_off + B + 1;
    int mc = MAXP * C;
    for (int idx = tid; idx < clus_n; idx += blockDim.x) {
        int b = idx / mc, rem = idx - b * mc;
        int slot = rem / C, c = rem - slot * C;
        int p = g_offs[b] + slot;
        out[idx] = (p < g_offs[b + 1]) ? __ldg(&feats[(size_t)p * C + c]) : 0.0f;
    }
    for (int idx = tid; idx < B * C; idx += blockDim.x) {
        int b = idx / C, c = idx - b * C;
        int sel = s_best[b];
        out[sf_off + idx] = (sel >= 0) ? __ldg(&feats[(size_t)sel * C + c]) : 0.0f;
    }
    if (tid < B)  out[spi_off + tid]  = (float)s_best[tid];
    if (tid <= B) out[offs_off + tid] = (float)g_offs[tid];
    if (tid < B)  out[good_off + tid] = ((s_max[tid] > 0.2f) && (__ldg(&pes[tid]) > 0)) ? 1.0f : 0.0f;
}

extern "C" void kernel_launch(void* const* d_in, const int* in_sizes, int n_in,
                              void* d_out, int out_size) {
    const int*   pidx   = (const int*)d_in[0];   // [M,2] int32
    const int*   pes    = (const int*)d_in[1];   // [B] int32
    const int*   labels = (const int*)d_in[2];   // [B*npoint] int32
    const int*   oid    = (const int*)d_in[3];   // [B] int32
    const float* feats  = (const float*)d_in[4]; // [PTOT, C] f32
    float* out = (float*)d_out;

    int M       = in_sizes[0] / 2;
    int B       = in_sizes[1];
    int n_total = in_sizes[2];
    int npoint  = n_total / B;
    int C       = 32;
    int PTOT    = in_sizes[4] / C;
    int npw     = (npoint + 31) / 32;

    int M2 = M / 2;
    int workA = M2 + 1;                       // +1 covers the odd-tail thread
    if (workA < n_total) workA = n_total;
    int gridA = (workA + 255) / 256;
    k_main<<<gridA, 256>>>((const int4*)pidx, (const int2*)pidx, labels, oid, pes,
                           M, M2, B, npoint, n_total, (unsigned)npoint);

    k_reduce<<<PTOT, 256>>>(B, npw);

    k_final<<<1, 256>>>(feats, pes, B, C, out);
}

// round 10
// speedup vs baseline: 1.6481x; 1.2523x over previous
#include <cuda_runtime.h>

#define NPW      2048      // 65536 points / 32 bits (words per proposal row)
#define PTOT_MAX 512
#define BMAX     8
#define MAXP     128

__device__ unsigned           g_pc_bits[PTOT_MAX * NPW]; // 4 MB bitmask; zeroed-on-read by k_reduce
__device__ unsigned           g_ref_bits[BMAX * NPW];    // per-scene reference bitmask (rewritten)
__device__ int                g_offs[BMAX + 1];
__device__ unsigned long long g_amax[BMAX];              // packed (iou_bits<<32 | 0x7fffffff-p); reset by k_final

// ---- Kernel A: scatter (2 pairs/thread, RED.OR) + ref ballot init + offsets ----
__global__ void __launch_bounds__(256, 8)
k_main(const int4* __restrict__ pidx2, const int2* __restrict__ pidx,
       const int* __restrict__ labels, const int* __restrict__ object_id,
       const int* __restrict__ pes,
       int M, int M2, int B, int npoint, int n_total, unsigned npu) {
    int t = blockIdx.x * blockDim.x + threadIdx.x;

    if (t == 0) {
        g_offs[0] = 0;
        for (int b = 0; b < B; b++) g_offs[b + 1] = g_offs[b] + __ldg(&pes[b]);
    }

    // --- reference bitmask via warp ballot (one label per thread) ---
    if (t < n_total) {
        int b = t / npoint;
        int oid = __ldg(&object_id[b]);
        int jl = t - b * npoint;
        unsigned wbase = (unsigned)(t & ~31);
        if (wbase + 32 <= (unsigned)n_total) {        // full warp, same scene (npoint%32==0)
            unsigned bits = __ballot_sync(0xffffffffu, __ldg(&labels[t]) == oid);
            if ((t & 31) == 0) g_ref_bits[b * NPW + (jl >> 5)] = bits;
        } else {                                      // ragged tail fallback
            if (__ldg(&labels[t]) == oid)
                atomicOr(&g_ref_bits[b * NPW + (jl >> 5)], 1u << (jl & 31u));
        }
    }

    // --- scatter: set bit (pid, j % npoint) ---
    if (t < M2) {
        int4 a = __ldg(&pidx2[t]);                    // two (pid, j) pairs
        unsigned j0 = (unsigned)a.y % npu;
        unsigned j1 = (unsigned)a.w % npu;
        atomicOr(&g_pc_bits[(size_t)a.x * NPW + (j0 >> 5)], 1u << (j0 & 31u));
        atomicOr(&g_pc_bits[(size_t)a.z * NPW + (j1 >> 5)], 1u << (j1 & 31u));
    }
    if ((M & 1) && t == M2) {                         // odd tail pair
        int2 v = __ldg(&pidx[M - 1]);
        unsigned j = (unsigned)v.y % npu;
        atomicOr(&g_pc_bits[(size_t)v.x * NPW + (j >> 5)], 1u << (j & 31u));
    }
}

// ---- Kernel B: block-per-proposal AND-popcount (uint4) + zero-on-read,
//      result folded into per-scene packed argmax via one RED.MAX.U64 per block.
__global__ void __launch_bounds__(256, 8)
k_reduce(int B, int npw) {
    int p = blockIdx.x;                              // proposal id (grid == PTOT)
    int tid = threadIdx.x;

    int b = 0;
    #pragma unroll
    for (int k = 1; k <= BMAX; k++) b += (k <= B && g_offs[k] <= p) ? 1 : 0;
    if (b >= B) b = B - 1;

    uint4* pcrow = (uint4*)(g_pc_bits + (size_t)p * NPW);
    const uint4* __restrict__ refrow = (const uint4*)(g_ref_bits + (size_t)b * NPW);
    int nq = npw >> 2;                               // uint4 chunks per row (512)
    unsigned cnt = 0, its = 0, rs = 0;
    const uint4 z = make_uint4(0u, 0u, 0u, 0u);
    #pragma unroll 2
    for (int w = tid; w < nq; w += 256) {
        uint4 v = pcrow[w];
        uint4 r = __ldg(&refrow[w]);
        pcrow[w] = z;                                // self-clean for next replay
        cnt += __popc(v.x) + __popc(v.y) + __popc(v.z) + __popc(v.w);
        its += __popc(v.x & r.x) + __popc(v.y & r.y)
             + __popc(v.z & r.z) + __popc(v.w & r.w);
        rs  += __popc(r.x) + __popc(r.y) + __popc(r.z) + __popc(r.w);
    }
    // word tail if npw % 4 != 0
    for (int w0 = (nq << 2) + tid; w0 < npw; w0 += 256) {
        unsigned v = g_pc_bits[(size_t)p * NPW + w0];
        unsigned r = g_ref_bits[(size_t)b * NPW + w0];
        g_pc_bits[(size_t)p * NPW + w0] = 0u;
        cnt += __popc(v); its += __popc(v & r); rs += __popc(r);
    }
    cnt = __reduce_add_sync(0xffffffffu, cnt);
    its = __reduce_add_sync(0xffffffffu, its);
    rs  = __reduce_add_sync(0xffffffffu, rs);
    __shared__ unsigned sc[8], si[8], sr[8];
    int warp = tid >> 5;
    if ((tid & 31) == 0) { sc[warp] = cnt; si[warp] = its; sr[warp] = rs; }
    __syncthreads();
    if (tid == 0) {
        unsigned Ct = 0, It = 0, Rt = 0;
        #pragma unroll
        for (int w = 0; w < 8; w++) { Ct += sc[w]; It += si[w]; Rt += sr[w]; }
        float inter = (float)It;
        float uni = (float)Ct + (float)Rt - inter;
        float iou = (uni > 0.0f) ? inter / fmaxf(uni, 1.0f) : 0.0f;
        // packed key: iou (non-negative float, bit-monotone) in high 32, tie -> smallest p
        unsigned long long key = ((unsigned long long)__float_as_uint(iou) << 32)
                               | (unsigned)(0x7fffffff - p);
        atomicMax(&g_amax[b], key);
    }
}

// ---- Kernel C: single-block epilogue — unpack argmax + all output writes + amax reset.
// Output layout (f32): [B*MAXP*C clus_feats | B*C select_feats | B sel_idx | B+1 offsets | B good]
__global__ void k_final(const float* __restrict__ feats, const int* __restrict__ pes,
                        int B, int C, float* __restrict__ out) {
    __shared__ int   s_best[BMAX];
    __shared__ float s_max[BMAX];
    int tid = threadIdx.x;
    if (tid < B) {
        unsigned long long key = g_amax[tid];
        g_amax[tid] = 0ull;                          // reset for next replay
        int   p   = 0x7fffffff - (int)(key & 0xffffffffull);
        float iou = __uint_as_float((unsigned)(key >> 32));
        bool has = (__ldg(&pes[tid]) > 0);
        s_best[tid] = has ? p : -1;
        s_max[tid]  = iou;
    }
    __syncthreads();
    int clus_n   = B * MAXP * C;
    int sf_off   = clus_n;
    int spi_off  = sf_off + B * C;
    int offs_off = spi_off + B;
    int good_off = offs_off + B + 1;
    int mc = MAXP * C;
    for (int idx = tid; idx < clus_n; idx += blockDim.x) {
        int b = idx / mc, rem = idx - b * mc;
        int slot = rem / C, c = rem - slot * C;
        int p = g_offs[b] + slot;
        out[idx] = (p < g_offs[b + 1]) ? __ldg(&feats[(size_t)p * C + c]) : 0.0f;
    }
    for (int idx = tid; idx < B * C; idx += blockDim.x) {
        int b = idx / C, c = idx - b * C;
        int sel = s_best[b];
        out[sf_off + idx] = (sel >= 0) ? __ldg(&feats[(size_t)sel * C + c]) : 0.0f;
    }
    if (tid < B)  out[spi_off + tid]  = (float)s_best[tid];
    if (tid <= B) out[offs_off + tid] = (float)g_offs[tid];
    if (tid < B)  out[good_off + tid] = ((s_max[tid] > 0.2f) && (__ldg(&pes[tid]) > 0)) ? 1.0f : 0.0f;
}

extern "C" void kernel_launch(void* const* d_in, const int* in_sizes, int n_in,
                              void* d_out, int out_size) {
    const int*   pidx   = (const int*)d_in[0];   // [M,2] int32
    const int*   pes    = (const int*)d_in[1];   // [B] int32
    const int*   labels = (const int*)d_in[2];   // [B*npoint] int32
    const int*   oid    = (const int*)d_in[3];   // [B] int32
    const float* feats  = (const float*)d_in[4]; // [PTOT, C] f32
    float* out = (float*)d_out;

    int M       = in_sizes[0] / 2;
    int B       = in_sizes[1];
    int n_total = in_sizes[2];
    int npoint  = n_total / B;
    int C       = 32;
    int PTOT    = in_sizes[4] / C;
    int npw     = (npoint + 31) / 32;

    int M2 = M / 2;
    int workA = M2 + 1;                       // +1 covers the odd-tail thread
    if (workA < n_total) workA = n_total;
    int gridA = (workA + 255) / 256;
    k_main<<<gridA, 256>>>((const int4*)pidx, (const int2*)pidx, labels, oid, pes,
                           M, M2, B, npoint, n_total, (unsigned)npoint);

    k_reduce<<<PTOT, 256>>>(B, npw);

    k_final<<<1, 512>>>(feats, pes, B, C, out);
}

// round 11
// speedup vs baseline: 2.1885x; 1.3279x over previous
#include <cuda_runtime.h>

#define NPW      2048      // 65536 points / 32 bits (words per proposal row)
#define PTOT_MAX 512
#define BMAX     8
#define MAXP     128

__device__ unsigned           g_pc_bits[PTOT_MAX * NPW]; // 4 MB bitmask; zeroed-on-read by k_reduce
__device__ unsigned           g_ref_bits[BMAX * NPW];    // per-scene reference bitmask (rewritten)
__device__ int                g_offs[BMAX + 1];
__device__ unsigned long long g_amax[BMAX];              // packed (iou_bits<<32 | 0x7fffffff-p); reset by k_main

// ---- Kernel A: scatter (2 pairs/thread, RED.OR) + ref ballot init + offsets + amax reset ----
__global__ void __launch_bounds__(256, 8)
k_main(const int4* __restrict__ pidx2, const int2* __restrict__ pidx,
       const int* __restrict__ labels, const int* __restrict__ object_id,
       const int* __restrict__ pes,
       int M, int M2, int B, int npoint, int n_total, unsigned npu) {
    int t = blockIdx.x * blockDim.x + threadIdx.x;

    if (t == 0) {
        g_offs[0] = 0;
        for (int b = 0; b < B; b++) g_offs[b + 1] = g_offs[b] + __ldg(&pes[b]);
    }
    if (t < BMAX) g_amax[t] = 0ull;                   // reset argmax keys for this replay

    // --- reference bitmask via warp ballot (one label per thread) ---
    if (t < n_total) {
        int b = t / npoint;
        int oid = __ldg(&object_id[b]);
        int jl = t - b * npoint;
        unsigned wbase = (unsigned)(t & ~31);
        if (wbase + 32 <= (unsigned)n_total) {        // full warp, same scene (npoint%32==0)
            unsigned bits = __ballot_sync(0xffffffffu, __ldg(&labels[t]) == oid);
            if ((t & 31) == 0) g_ref_bits[b * NPW + (jl >> 5)] = bits;
        } else {                                      // ragged tail fallback
            if (__ldg(&labels[t]) == oid)
                atomicOr(&g_ref_bits[b * NPW + (jl >> 5)], 1u << (jl & 31u));
        }
    }

    // --- scatter: set bit (pid, j % npoint); streaming loads protect L2 for the RMW lines ---
    if (t < M2) {
        int4 a = __ldcs(&pidx2[t]);                   // two (pid, j) pairs, evict-first
        unsigned j0 = (unsigned)a.y % npu;
        unsigned j1 = (unsigned)a.w % npu;
        atomicOr(&g_pc_bits[(size_t)a.x * NPW + (j0 >> 5)], 1u << (j0 & 31u));
        atomicOr(&g_pc_bits[(size_t)a.z * NPW + (j1 >> 5)], 1u << (j1 & 31u));
    }
    if ((M & 1) && t == M2) {                         // odd tail pair
        int2 v = __ldg(&pidx[M - 1]);
        unsigned j = (unsigned)v.y % npu;
        atomicOr(&g_pc_bits[(size_t)v.x * NPW + (j >> 5)], 1u << (j & 31u));
    }
}

// ---- Kernel B: block-per-proposal AND-popcount (uint4) + zero-on-read,
//      result folded into per-scene packed argmax via one RED.MAX.U64 per block.
__global__ void __launch_bounds__(256, 8)
k_reduce(int B, int npw) {
    int p = blockIdx.x;                              // proposal id (grid == PTOT)
    int tid = threadIdx.x;

    int b = 0;
    #pragma unroll
    for (int k = 1; k <= BMAX; k++) b += (k <= B && g_offs[k] <= p) ? 1 : 0;
    if (b >= B) b = B - 1;

    uint4* pcrow = (uint4*)(g_pc_bits + (size_t)p * NPW);
    const uint4* __restrict__ refrow = (const uint4*)(g_ref_bits + (size_t)b * NPW);
    int nq = npw >> 2;                               // uint4 chunks per row (512)
    unsigned cnt = 0, its = 0, rs = 0;
    const uint4 z = make_uint4(0u, 0u, 0u, 0u);
    #pragma unroll 2
    for (int w = tid; w < nq; w += 256) {
        uint4 v = pcrow[w];
        uint4 r = __ldg(&refrow[w]);
        pcrow[w] = z;                                // self-clean for next replay
        cnt += __popc(v.x) + __popc(v.y) + __popc(v.z) + __popc(v.w);
        its += __popc(v.x & r.x) + __popc(v.y & r.y)
             + __popc(v.z & r.z) + __popc(v.w & r.w);
        rs  += __popc(r.x) + __popc(r.y) + __popc(r.z) + __popc(r.w);
    }
    // word tail if npw % 4 != 0
    for (int w0 = (nq << 2) + tid; w0 < npw; w0 += 256) {
        unsigned v = g_pc_bits[(size_t)p * NPW + w0];
        unsigned r = g_ref_bits[(size_t)b * NPW + w0];
        g_pc_bits[(size_t)p * NPW + w0] = 0u;
        cnt += __popc(v); its += __popc(v & r); rs += __popc(r);
    }
    cnt = __reduce_add_sync(0xffffffffu, cnt);
    its = __reduce_add_sync(0xffffffffu, its);
    rs  = __reduce_add_sync(0xffffffffu, rs);
    __shared__ unsigned sc[8], si[8], sr[8];
    int warp = tid >> 5;
    if ((tid & 31) == 0) { sc[warp] = cnt; si[warp] = its; sr[warp] = rs; }
    __syncthreads();
    if (tid == 0) {
        unsigned Ct = 0, It = 0, Rt = 0;
        #pragma unroll
        for (int w = 0; w < 8; w++) { Ct += sc[w]; It += si[w]; Rt += sr[w]; }
        float inter = (float)It;
        float uni = (float)Ct + (float)Rt - inter;
        float iou = (uni > 0.0f) ? inter / fmaxf(uni, 1.0f) : 0.0f;
        // packed key: iou (non-negative float, bit-monotone) in high 32, tie -> smallest p
        unsigned long long key = ((unsigned long long)__float_as_uint(iou) << 32)
                               | (unsigned)(0x7fffffff - p);
        atomicMax(&g_amax[b], key);
    }
}

// ---- Kernel C: stateless parallel epilogue (64 blocks) — every block unpacks g_amax.
// Output layout (f32): [B*MAXP*C clus_feats | B*C select_feats | B sel_idx | B+1 offsets | B good]
__global__ void __launch_bounds__(256)
k_final(const float* __restrict__ feats, const int* __restrict__ pes,
        int B, int C, float* __restrict__ out) {
    __shared__ int   s_best[BMAX];
    __shared__ float s_max[BMAX];
    int tid = threadIdx.x;
    if (tid < B) {
        unsigned long long key = g_amax[tid];        // read-only: reset happens in k_main
        int   p   = 0x7fffffff - (int)(key & 0xffffffffull);
        float iou = __uint_as_float((unsigned)(key >> 32));
        s_best[tid] = (__ldg(&pes[tid]) > 0) ? p : -1;
        s_max[tid]  = iou;
    }
    __syncthreads();
    int clus_n   = B * MAXP * C;
    int sf_off   = clus_n;
    int spi_off  = sf_off + B * C;
    int offs_off = spi_off + B;
    int good_off = offs_off + B + 1;
    int mc = MAXP * C;
    int gtid = blockIdx.x * blockDim.x + tid;
    int gstride = gridDim.x * blockDim.x;
    for (int idx = gtid; idx < clus_n; idx += gstride) {
        int b = idx / mc, rem = idx - b * mc;
        int slot = rem / C, c = rem - slot * C;
        int p = g_offs[b] + slot;
        out[idx] = (p < g_offs[b + 1]) ? __ldg(&feats[(size_t)p * C + c]) : 0.0f;
    }
    for (int idx = gtid; idx < B * C; idx += gstride) {
        int b = idx / C, c = idx - b * C;
        int sel = s_best[b];
        out[sf_off + idx] = (sel >= 0) ? __ldg(&feats[(size_t)sel * C + c]) : 0.0f;
    }
    if (blockIdx.x == 0) {
        if (tid < B)  out[spi_off + tid]  = (float)s_best[tid];
        if (tid <= B) out[offs_off + tid] = (float)g_offs[tid];
        if (tid < B)  out[good_off + tid] = ((s_max[tid] > 0.2f) && (__ldg(&pes[tid]) > 0)) ? 1.0f : 0.0f;
    }
}

extern "C" void kernel_launch(void* const* d_in, const int* in_sizes, int n_in,
                              void* d_out, int out_size) {
    const int*   pidx   = (const int*)d_in[0];   // [M,2] int32
    const int*   pes    = (const int*)d_in[1];   // [B] int32
    const int*   labels = (const int*)d_in[2];   // [B*npoint] int32
    const int*   oid    = (const int*)d_in[3];   // [B] int32
    const float* feats  = (const float*)d_in[4]; // [PTOT, C] f32
    float* out = (float*)d_out;

    int M       = in_sizes[0] / 2;
    int B       = in_sizes[1];
    int n_total = in_sizes[2];
    int npoint  = n_total / B;
    int C       = 32;
    int PTOT    = in_sizes[4] / C;
    int npw     = (npoint + 31) / 32;

    int M2 = M / 2;
    int workA = M2 + 1;                       // +1 covers the odd-tail thread
    if (workA < n_total) workA = n_total;
    int gridA = (workA + 255) / 256;
    k_main<<<gridA, 256>>>((const int4*)pidx, (const int2*)pidx, labels, oid, pes,
                           M, M2, B, npoint, n_total, (unsigned)npoint);

    k_reduce<<<PTOT, 256>>>(B, npw);

    k_final<<<64, 256>>>(feats, pes, B, C, out);
}

// round 13
// speedup vs baseline: 2.3421x; 1.0702x over previous
#include <cuda_runtime.h>

#define NPW      2048      // 65536 points / 32 bits (words per proposal row)
#define PTOT_MAX 512
#define BMAX     8
#define MAXP     128

__device__ unsigned           g_pc_bits[PTOT_MAX * NPW]; // 4 MB bitmask; zeroed-on-read by k_reduce
__device__ unsigned           g_ref_bits[BMAX * NPW];    // per-scene reference bitmask (rewritten)
__device__ int                g_offs[BMAX + 1];
__device__ unsigned long long g_amax[BMAX];              // packed (iou_bits<<32 | 0x7fffffff-p); reset by k_main

// ---- Kernel A: scatter (2 pairs/thread, RED.OR) + ref ballot init + offsets + amax reset ----
__global__ void __launch_bounds__(256, 8)
k_main(const int4* __restrict__ pidx2, const int2* __restrict__ pidx,
       const int* __restrict__ labels, const int* __restrict__ object_id,
       const int* __restrict__ pes,
       int M, int M2, int B, int npoint, int n_total, unsigned npu) {
    int t = blockIdx.x * blockDim.x + threadIdx.x;

    if (t == 0) {
        g_offs[0] = 0;
        for (int b = 0; b < B; b++) g_offs[b + 1] = g_offs[b] + __ldg(&pes[b]);
    }
    if (t < BMAX) g_amax[t] = 0ull;                   // reset argmax keys for this replay

    // --- reference bitmask via warp ballot (one label per thread) ---
    if (t < n_total) {
        int b = t / npoint;
        int oid = __ldg(&object_id[b]);
        int jl = t - b * npoint;
        unsigned wbase = (unsigned)(t & ~31);
        if (wbase + 32 <= (unsigned)n_total) {        // full warp, same scene (npoint%32==0)
            unsigned bits = __ballot_sync(0xffffffffu, __ldg(&labels[t]) == oid);
            if ((t & 31) == 0) g_ref_bits[b * NPW + (jl >> 5)] = bits;
        } else {                                      // ragged tail fallback
            if (__ldg(&labels[t]) == oid)
                atomicOr(&g_ref_bits[b * NPW + (jl >> 5)], 1u << (jl & 31u));
        }
    }

    // --- scatter: set bit (pid, j % npoint); streaming loads protect L2 for the RMW lines ---
    if (t < M2) {
        int4 a = __ldcs(&pidx2[t]);                   // two (pid, j) pairs, evict-first
        unsigned j0 = (unsigned)a.y % npu;
        unsigned j1 = (unsigned)a.w % npu;
        atomicOr(&g_pc_bits[(size_t)a.x * NPW + (j0 >> 5)], 1u << (j0 & 31u));
        atomicOr(&g_pc_bits[(size_t)a.z * NPW + (j1 >> 5)], 1u << (j1 & 31u));
    }
    if ((M & 1) && t == M2) {                         // odd tail pair
        int2 v = __ldg(&pidx[M - 1]);
        unsigned j = (unsigned)v.y % npu;
        atomicOr(&g_pc_bits[(size_t)v.x * NPW + (j >> 5)], 1u << (j & 31u));
    }
}

// ---- Kernel B: block-per-proposal AND-popcount (uint4) + zero-on-read + packed argmax,
//      plus clus_feats_batch writes (block p <-> (scene, slot); depends only on g_offs).
__global__ void __launch_bounds__(256, 8)
k_reduce(int B, int npw, int PTOT, int C, const float* __restrict__ feats,
         float* __restrict__ out) {
    cudaGridDependencySynchronize();                 // PDL guard: wait for k_main's memory
    int p = blockIdx.x;
    int tid = threadIdx.x;

    if (p < PTOT) {
        int b = 0;
        #pragma unroll
        for (int k = 1; k <= BMAX; k++) b += (k <= B && g_offs[k] <= p) ? 1 : 0;
        if (b >= B) b = B - 1;

        uint4* pcrow = (uint4*)(g_pc_bits + (size_t)p * NPW);
        const uint4* __restrict__ refrow = (const uint4*)(g_ref_bits + (size_t)b * NPW);
        int nq = npw >> 2;                           // uint4 chunks per row (512)
        unsigned cnt = 0, its = 0, rs = 0;
        const uint4 z = make_uint4(0u, 0u, 0u, 0u);
        #pragma unroll 2
        for (int w = tid; w < nq; w += 256) {
            uint4 v = pcrow[w];
            uint4 r = __ldg(&refrow[w]);
            pcrow[w] = z;                            // self-clean for next replay
            cnt += __popc(v.x) + __popc(v.y) + __popc(v.z) + __popc(v.w);
            its += __popc(v.x & r.x) + __popc(v.y & r.y)
                 + __popc(v.z & r.z) + __popc(v.w & r.w);
            rs  += __popc(r.x) + __popc(r.y) + __popc(r.z) + __popc(r.w);
        }
        for (int w0 = (nq << 2) + tid; w0 < npw; w0 += 256) {  // word tail (npw % 4)
            unsigned v = g_pc_bits[(size_t)p * NPW + w0];
            unsigned r = g_ref_bits[(size_t)b * NPW + w0];
            g_pc_bits[(size_t)p * NPW + w0] = 0u;
            cnt += __popc(v); its += __popc(v & r); rs += __popc(r);
        }
        cnt = __reduce_add_sync(0xffffffffu, cnt);
        its = __reduce_add_sync(0xffffffffu, its);
        rs  = __reduce_add_sync(0xffffffffu, rs);
        __shared__ unsigned sc[8], si[8], sr[8];
        int warp = tid >> 5;
        if ((tid & 31) == 0) { sc[warp] = cnt; si[warp] = its; sr[warp] = rs; }
        __syncthreads();
        if (tid == 0) {
            unsigned Ct = 0, It = 0, Rt = 0;
            #pragma unroll
            for (int w = 0; w < 8; w++) { Ct += sc[w]; It += si[w]; Rt += sr[w]; }
            float inter = (float)It;
            float uni = (float)Ct + (float)Rt - inter;
            float iou = (uni > 0.0f) ? inter / fmaxf(uni, 1.0f) : 0.0f;
            // packed key: iou (non-negative float, bit-monotone) high 32; tie -> smallest p
            unsigned long long key = ((unsigned long long)__float_as_uint(iou) << 32)
                                   | (unsigned)(0x7fffffff - p);
            atomicMax(&g_amax[b], key);
        }
    }

    // --- clus_feats_batch[b2, slot] = feats[offs[b2]+slot] (zeros past scene end) ---
    int b2 = p / MAXP, slot = p - b2 * MAXP;         // grid covers max(PTOT, B*MAXP)
    if (b2 < B) {
        int lo = g_offs[b2], hi = g_offs[b2 + 1];
        int pp = lo + slot;
        bool valid = (slot < hi - lo);
        float* dst = out + (size_t)(b2 * MAXP + slot) * C;
        const float* src = feats + (size_t)pp * C;
        for (int c = tid; c < C; c += 256)
            dst[c] = valid ? __ldg(&src[c]) : 0.0f;
    }
}

// ---- Kernel C: tiny epilogue — select_feats + scalar outputs.
// Output layout (f32): [B*MAXP*C clus_feats | B*C select_feats | B sel_idx | B+1 offsets | B good]
__global__ void __launch_bounds__(128)
k_final(const float* __restrict__ feats, const int* __restrict__ pes,
        int B, int C, float* __restrict__ out) {
    cudaGridDependencySynchronize();                 // PDL guard: wait for k_reduce's memory
    __shared__ int   s_best[BMAX];
    __shared__ float s_max[BMAX];
    int tid = threadIdx.x;
    if (tid < B) {
        unsigned long long key = g_amax[tid];
        int   p   = 0x7fffffff - (int)(key & 0xffffffffull);
        float iou = __uint_as_float((unsigned)(key >> 32));
        s_best[tid] = (__ldg(&pes[tid]) > 0) ? p : -1;
        s_max[tid]  = iou;
    }
    __syncthreads();
    int sf_off   = B * MAXP * C;
    int spi_off  = sf_off + B * C;
    int offs_off = spi_off + B;
    int good_off = offs_off + B + 1;
    for (int idx = tid; idx < B * C; idx += blockDim.x) {
        int b = idx / C, c = idx - b * C;
        int sel = s_best[b];
        out[sf_off + idx] = (sel >= 0) ? __ldg(&feats[(size_t)sel * C + c]) : 0.0f;
    }
    if (tid < B)  out[spi_off + tid]  = (float)s_best[tid];
    if (tid <= B) out[offs_off + tid] = (float)g_offs[tid];
    if (tid < B)  out[good_off + tid] = ((s_max[tid] > 0.2f) && (__ldg(&pes[tid]) > 0)) ? 1.0f : 0.0f;
}

extern "C" void kernel_launch(void* const* d_in, const int* in_sizes, int n_in,
                              void* d_out, int out_size) {
    const int*   pidx   = (const int*)d_in[0];   // [M,2] int32
    const int*   pes    = (const int*)d_in[1];   // [B] int32
    const int*   labels = (const int*)d_in[2];   // [B*npoint] int32
    const int*   oid    = (const int*)d_in[3];   // [B] int32
    const float* feats  = (const float*)d_in[4]; // [PTOT, C] f32
    float* out = (float*)d_out;

    int M       = in_sizes[0] / 2;
    int B       = in_sizes[1];
    int n_total = in_sizes[2];
    int npoint  = n_total / B;
    int C       = 32;
    int PTOT    = in_sizes[4] / C;
    int npw     = (npoint + 31) / 32;

    int M2 = M / 2;
    int workA = M2 + 1;                       // +1 covers the odd-tail thread
    if (workA < n_total) workA = n_total;
    int gridA = (workA + 255) / 256;
    k_main<<<gridA, 256>>>((const int4*)pidx, (const int2*)pidx, labels, oid, pes,
                           M, M2, B, npoint, n_total, (unsigned)npoint);

    // PDL attribute: allow dependent launch to overlap predecessor drain
    cudaLaunchAttribute attrs[1];
    attrs[0].id = cudaLaunchAttributeProgrammaticStreamSerialization;
    attrs[0].val.programmaticStreamSerializationAllowed = 1;

    int gridB = PTOT > B * MAXP ? PTOT : B * MAXP;
    {
        cudaLaunchConfig_t cfg = {};
        cfg.gridDim  = dim3((unsigned)gridB, 1, 1);
        cfg.blockDim = dim3(256, 1, 1);
        cfg.attrs = attrs; cfg.numAttrs = 1;
        cudaLaunchKernelEx(&cfg, k_reduce, B, npw, PTOT, C, feats, out);
    }
    {
        cudaLaunchConfig_t cfg = {};
        cfg.gridDim  = dim3(1, 1, 1);
        cfg.blockDim = dim3(128, 1, 1);
        cfg.attrs = attrs; cfg.numAttrs = 1;
        cudaLaunchKernelEx(&cfg, k_final, feats, pes, B, C, out);
    }
}